// round 9
// baseline (speedup 1.0000x reference)
#include <cuda_runtime.h>
#include <cstdint>

// Problem dims
#define T_STEPS 256
#define BATCH   128
#define INDIM   1024
#define HID     1024
#define OUTDIM  256
#define MROWS   (T_STEPS * BATCH)   // 32768
#define BETA_F  0.9f
#define KC      512                 // Eigen gebp panel depth (bit-exactness contract)

// Scratch (allocation-free rule: __device__ globals)
__device__ float g_cur1[(size_t)MROWS * HID];     // 128 MB
__device__ float g_cur2[(size_t)MROWS * OUTDIM];  // 32 MB
__device__ float g_xT  [(size_t)INDIM * MROWS];   // 128 MB  x transposed (k-major)
__device__ float g_w1T [(size_t)INDIM * HID];     // 4 MB    w1 transposed
__device__ float g_w2T [(size_t)HID * OUTDIM];    // 1 MB    w2 transposed

typedef unsigned long long ull;

// ---- packed f32x2 helpers (each lane = independent IEEE fp32 rn op) --------
__device__ __forceinline__ void ffma2(ull& d, ull a, ull b) {
    asm("fma.rn.f32x2 %0, %1, %2, %0;" : "+l"(d) : "l"(a), "l"(b));
}
__device__ __forceinline__ ull bcast2(float x) {
    ull r; asm("mov.b64 %0, {%1, %1};" : "=l"(r) : "f"(x)); return r;
}
__device__ __forceinline__ void unpack2(float& lo, float& hi, ull v) {
    asm("mov.b64 {%0, %1}, %2;" : "=f"(lo), "=f"(hi) : "l"(v));
}

// ---- cp.async helpers ------------------------------------------------------
__device__ __forceinline__ void cp_async16(uint32_t smem, const void* g) {
    asm volatile("cp.async.cg.shared.global [%0], [%1], 16;" :: "r"(smem), "l"(g));
}
__device__ __forceinline__ void cp_commit() {
    asm volatile("cp.async.commit_group;" ::: "memory");
}
template<int N>
__device__ __forceinline__ void cp_wait() {
    asm volatile("cp.async.wait_group %0;" :: "n"(N) : "memory");
}

// ---------------------------------------------------------------------------
// Tiled transpose: in [rows][cols] -> out [cols][rows]. Pure bit copy.
// ---------------------------------------------------------------------------
__global__ void transpose32(const float* __restrict__ in, float* __restrict__ out,
                            int rows, int cols)
{
    __shared__ float tile[32][33];
    const int c0 = blockIdx.x * 32;
    const int r0 = blockIdx.y * 32;
    #pragma unroll
    for (int j = 0; j < 32; j += 8)
        tile[threadIdx.y + j][threadIdx.x] =
            in[(size_t)(r0 + threadIdx.y + j) * cols + c0 + threadIdx.x];
    __syncthreads();
    #pragma unroll
    for (int j = 0; j < 32; j += 8)
        out[(size_t)(c0 + threadIdx.y + j) * rows + r0 + threadIdx.x] =
            tile[threadIdx.x][threadIdx.y + j];
}

// ---------------------------------------------------------------------------
// SGEMM NT panel (kc=512), FFMA2, cp.async tile loads.
// Numerics contract (bit-match Eigen gebp kc=512, VERIFIED rel_err==0):
//   per element: S = fadd( chain(k=0..511), chain(k=512..1023) ), chains are
//   ascending-k fp32 FMA chains from 0; then ONE rounded bias add (phase 1).
// AMODE 0: A,B both k-major -> pure cp.async, 3-stage ring, wait_group 1.
// AMODE 1: A m-major (spk1) -> 2-stage, LDG-staged A + STS, cp.async B.
// Tile 128x128x16, 256 threads, microtile 8m(4 f32x2 m-pairs) x 8n.
// ---------------------------------------------------------------------------
#define BM 128
#define BN 128
#define BK 16
#define NITER (KC / BK)   // 32

template<int AMODE>
__global__ __launch_bounds__(256, 2)
void sgemm_panel(const float* __restrict__ A,
                 const float* __restrict__ B,
                 const float* __restrict__ bias,
                 float* __restrict__ C,
                 int lda, int ldb, int N, int addBias)
{
    constexpr int STAGES = (AMODE == 0) ? 3 : 2;
    __shared__ __align__(16) float As[STAGES][BK][BM];
    __shared__ __align__(16) float Bs[STAGES][BK][BN];

    const int tid = threadIdx.x;
    const int bm = blockIdx.y * BM;
    const int bn = blockIdx.x * BN;

    // compute indexing: quadrant layout
    const int tx = (tid & 15) << 2;   // n base (4 wide); second group at +64
    const int ty = (tid >> 4) << 2;   // m base (4 tall); second group at +64

    // cp.async chunk indexing: 16x128-float tile = 512 chunks of 16B
    const int lk  = tid >> 5;          // 0..7
    const int lof = (tid & 31) << 2;   // 0..124

    // AMODE 1 staging indexing
    const int lr = tid >> 2;           // 0..63
    const int lc = (tid & 3) << 2;     // 0,4,8,12

    const uint32_t sA = (uint32_t)__cvta_generic_to_shared(&As[0][0][0]);
    const uint32_t sB = (uint32_t)__cvta_generic_to_shared(&Bs[0][0][0]);
    #define SA_ADDR(b, k, off) (sA + (uint32_t)(((b) * BK + (k)) * BM + (off)) * 4u)
    #define SB_ADDR(b, k, off) (sB + (uint32_t)(((b) * BK + (k)) * BN + (off)) * 4u)

    ull acc[4][8];   // panel chains: 4 m-pairs x 8 n
    #pragma unroll
    for (int i = 0; i < 4; i++)
        #pragma unroll
        for (int j = 0; j < 8; j++) acc[i][j] = 0ull;

    if (AMODE == 0) {
        // ---- 3-stage ring, pure cp.async ----
        #pragma unroll
        for (int s = 0; s < STAGES - 1; s++) {
            const int kt = s * BK;
            cp_async16(SB_ADDR(s, lk, lof),     &B[(size_t)(kt + lk) * ldb + bn + lof]);
            cp_async16(SB_ADDR(s, lk + 8, lof), &B[(size_t)(kt + lk + 8) * ldb + bn + lof]);
            cp_async16(SA_ADDR(s, lk, lof),     &A[(size_t)(kt + lk) * lda + bm + lof]);
            cp_async16(SA_ADDR(s, lk + 8, lof), &A[(size_t)(kt + lk + 8) * lda + bm + lof]);
            cp_commit();
        }

        for (int iter = 0; iter < NITER; iter++) {
            // tile `iter` was committed >= 2 groups ago; <=1 group may remain in flight
            cp_wait<STAGES - 2>();
            __syncthreads();

            // issue tile iter+STAGES-1 into ring slot (safe: that slot was last
            // read at iter-1, which completed before the sync above)
            if (iter + STAGES - 1 < NITER) {
                const int kt = (iter + STAGES - 1) * BK;
                const int nb = (iter + STAGES - 1) % STAGES;
                cp_async16(SB_ADDR(nb, lk, lof),     &B[(size_t)(kt + lk) * ldb + bn + lof]);
                cp_async16(SB_ADDR(nb, lk + 8, lof), &B[(size_t)(kt + lk + 8) * ldb + bn + lof]);
                cp_async16(SA_ADDR(nb, lk, lof),     &A[(size_t)(kt + lk) * lda + bm + lof]);
                cp_async16(SA_ADDR(nb, lk + 8, lof), &A[(size_t)(kt + lk + 8) * lda + bm + lof]);
                cp_commit();
            }

            const int buf = iter % STAGES;
            #pragma unroll
            for (int k = 0; k < BK; k++) {
                ulonglong2 av0 = *reinterpret_cast<const ulonglong2*>(&As[buf][k][ty]);
                ulonglong2 av1 = *reinterpret_cast<const ulonglong2*>(&As[buf][k][ty + 64]);
                float4 b0 = *reinterpret_cast<const float4*>(&Bs[buf][k][tx]);
                float4 b1 = *reinterpret_cast<const float4*>(&Bs[buf][k][tx + 64]);
                ull ap[4] = {av0.x, av0.y, av1.x, av1.y};
                ull bb[8];
                bb[0] = bcast2(b0.x); bb[1] = bcast2(b0.y);
                bb[2] = bcast2(b0.z); bb[3] = bcast2(b0.w);
                bb[4] = bcast2(b1.x); bb[5] = bcast2(b1.y);
                bb[6] = bcast2(b1.z); bb[7] = bcast2(b1.w);
                #pragma unroll
                for (int i = 0; i < 4; i++)
                    #pragma unroll
                    for (int j = 0; j < 8; j++)
                        ffma2(acc[i][j], ap[i], bb[j]);
            }
        }
    } else {
        // ---- 2-stage: LDG-staged A transpose + cp.async B (R8-proven) ----
        cp_async16(SB_ADDR(0, lk, lof),     &B[(size_t)lk * ldb + bn + lof]);
        cp_async16(SB_ADDR(0, lk + 8, lof), &B[(size_t)(lk + 8) * ldb + bn + lof]);
        {
            float4 a0 = *reinterpret_cast<const float4*>(&A[(size_t)(bm + lr) * lda + lc]);
            float4 a1 = *reinterpret_cast<const float4*>(&A[(size_t)(bm + lr + 64) * lda + lc]);
            As[0][lc + 0][lr] = a0.x; As[0][lc + 1][lr] = a0.y;
            As[0][lc + 2][lr] = a0.z; As[0][lc + 3][lr] = a0.w;
            As[0][lc + 0][lr + 64] = a1.x; As[0][lc + 1][lr + 64] = a1.y;
            As[0][lc + 2][lr + 64] = a1.z; As[0][lc + 3][lr + 64] = a1.w;
        }
        cp_commit();
        cp_wait<0>();
        __syncthreads();

        int buf = 0;
        for (int iter = 0; iter < NITER; iter++) {
            float4 stA0, stA1;
            if (iter + 1 < NITER) {
                const int kt = (iter + 1) * BK;
                const int nb = buf ^ 1;
                cp_async16(SB_ADDR(nb, lk, lof),     &B[(size_t)(kt + lk) * ldb + bn + lof]);
                cp_async16(SB_ADDR(nb, lk + 8, lof), &B[(size_t)(kt + lk + 8) * ldb + bn + lof]);
                stA0 = *reinterpret_cast<const float4*>(&A[(size_t)(bm + lr) * lda + kt + lc]);
                stA1 = *reinterpret_cast<const float4*>(&A[(size_t)(bm + lr + 64) * lda + kt + lc]);
                cp_commit();
            }

            #pragma unroll
            for (int k = 0; k < BK; k++) {
                ulonglong2 av0 = *reinterpret_cast<const ulonglong2*>(&As[buf][k][ty]);
                ulonglong2 av1 = *reinterpret_cast<const ulonglong2*>(&As[buf][k][ty + 64]);
                float4 b0 = *reinterpret_cast<const float4*>(&Bs[buf][k][tx]);
                float4 b1 = *reinterpret_cast<const float4*>(&Bs[buf][k][tx + 64]);
                ull ap[4] = {av0.x, av0.y, av1.x, av1.y};
                ull bb[8];
                bb[0] = bcast2(b0.x); bb[1] = bcast2(b0.y);
                bb[2] = bcast2(b0.z); bb[3] = bcast2(b0.w);
                bb[4] = bcast2(b1.x); bb[5] = bcast2(b1.y);
                bb[6] = bcast2(b1.z); bb[7] = bcast2(b1.w);
                #pragma unroll
                for (int i = 0; i < 4; i++)
                    #pragma unroll
                    for (int j = 0; j < 8; j++)
                        ffma2(acc[i][j], ap[i], bb[j]);
            }

            if (iter + 1 < NITER) {
                const int nb = buf ^ 1;
                As[nb][lc + 0][lr] = stA0.x; As[nb][lc + 1][lr] = stA0.y;
                As[nb][lc + 2][lr] = stA0.z; As[nb][lc + 3][lr] = stA0.w;
                As[nb][lc + 0][lr + 64] = stA1.x; As[nb][lc + 1][lr + 64] = stA1.y;
                As[nb][lc + 2][lr + 64] = stA1.z; As[nb][lc + 3][lr + 64] = stA1.w;
                cp_wait<0>();
                __syncthreads();
                buf = nb;
            }
        }
    }

    // ---- epilogue ----
    if (addBias) {
        // phase 1: v = fadd( fadd(C_panel1, acc_panel2), bias ), per element
        float4 bv0 = *reinterpret_cast<const float4*>(&bias[bn + tx]);
        float4 bv1 = *reinterpret_cast<const float4*>(&bias[bn + tx + 64]);
        const float bb[8] = {bv0.x, bv0.y, bv0.z, bv0.w, bv1.x, bv1.y, bv1.z, bv1.w};
        #pragma unroll
        for (int i = 0; i < 4; i++) {
            int r0 = bm + ((i < 2) ? (ty + 2 * i) : (ty + 64 + 2 * (i - 2)));
            #pragma unroll
            for (int half = 0; half < 2; half++) {
                int row = r0 + half;
                float4 p0 = *reinterpret_cast<const float4*>(&C[(size_t)row * N + bn + tx]);
                float4 p1 = *reinterpret_cast<const float4*>(&C[(size_t)row * N + bn + tx + 64]);
                float pr[8] = {p0.x, p0.y, p0.z, p0.w, p1.x, p1.y, p1.z, p1.w};
                float o[8];
                #pragma unroll
                for (int j = 0; j < 8; j++) {
                    float lo, hi;
                    unpack2(lo, hi, acc[i][j]);
                    float mine = half ? hi : lo;
                    o[j] = __fadd_rn(__fadd_rn(pr[j], mine), bb[j]);
                }
                float4 s0 = {o[0], o[1], o[2], o[3]};
                float4 s1 = {o[4], o[5], o[6], o[7]};
                *reinterpret_cast<float4*>(&C[(size_t)row * N + bn + tx]) = s0;
                *reinterpret_cast<float4*>(&C[(size_t)row * N + bn + tx + 64]) = s1;
            }
        }
    } else {
        // phase 0: store raw panel-1 partials (exact bits)
        #pragma unroll
        for (int i = 0; i < 4; i++) {
            int r0 = bm + ((i < 2) ? (ty + 2 * i) : (ty + 64 + 2 * (i - 2)));
            float lo[8], hi[8];
            #pragma unroll
            for (int j = 0; j < 8; j++) unpack2(lo[j], hi[j], acc[i][j]);
            float4 s0 = {lo[0], lo[1], lo[2], lo[3]};
            float4 s1 = {lo[4], lo[5], lo[6], lo[7]};
            float4 s2 = {hi[0], hi[1], hi[2], hi[3]};
            float4 s3 = {hi[4], hi[5], hi[6], hi[7]};
            *reinterpret_cast<float4*>(&C[(size_t)r0 * N + bn + tx]) = s0;
            *reinterpret_cast<float4*>(&C[(size_t)r0 * N + bn + tx + 64]) = s1;
            *reinterpret_cast<float4*>(&C[(size_t)(r0 + 1) * N + bn + tx]) = s2;
            *reinterpret_cast<float4*>(&C[(size_t)(r0 + 1) * N + bn + tx + 64]) = s3;
        }
    }
    #undef SA_ADDR
    #undef SB_ADDR
}

// ---------------------------------------------------------------------------
// LIF recurrence, XLA-exact op ordering per lane (no FMA contraction).
// ---------------------------------------------------------------------------
__device__ __forceinline__ void lif_step(float& mem, float& s, float c, float thr) {
    float t0 = __fmul_rn(BETA_F, mem);
    float t1 = __fadd_rn(t0, c);
    float t2 = __fmul_rn(s, thr);
    mem = __fsub_rn(t1, t2);
    s = (__fsub_rn(mem, thr) > 0.f) ? 1.0f : 0.0f;
}

__global__ void lif_scan4(const float4* __restrict__ cur,
                          const float* __restrict__ thr_p,
                          float4* __restrict__ spk_rec,
                          int stride4)
{
    const int idx = blockIdx.x * blockDim.x + threadIdx.x;
    const float thr = *thr_p;
    float4 mem = {0.f, 0.f, 0.f, 0.f};
    float4 s   = {0.f, 0.f, 0.f, 0.f};
    const float4* p = cur + idx;
    float4* q = spk_rec + idx;
    float4 c = p[0];
    #pragma unroll 4
    for (int t = 0; t < T_STEPS; t++) {
        float4 cn = {0.f, 0.f, 0.f, 0.f};
        if (t + 1 < T_STEPS) cn = p[(size_t)(t + 1) * stride4];
        lif_step(mem.x, s.x, c.x, thr);
        lif_step(mem.y, s.y, c.y, thr);
        lif_step(mem.z, s.z, c.z, thr);
        lif_step(mem.w, s.w, c.w, thr);
        q[(size_t)t * stride4] = s;
        c = cn;
    }
}

__global__ void lif_scan1(const float* __restrict__ cur,
                          const float* __restrict__ thr_p,
                          float* __restrict__ spk_rec,
                          int stride)
{
    const int idx = blockIdx.x * blockDim.x + threadIdx.x;
    const float thr = *thr_p;
    float mem = 0.f, s = 0.f;
    const float* p = cur + idx;
    float* q = spk_rec + idx;
    float c = p[0];
    #pragma unroll 8
    for (int t = 0; t < T_STEPS; t++) {
        float cn = 0.f;
        if (t + 1 < T_STEPS) cn = p[(size_t)(t + 1) * stride];
        lif_step(mem, s, c, thr);
        q[(size_t)t * stride] = s;
        c = cn;
    }
}

// ---------------------------------------------------------------------------
extern "C" void kernel_launch(void* const* d_in, const int* in_sizes, int n_in,
                              void* d_out, int out_size)
{
    const float* x    = (const float*)d_in[0];  // [T,B,I]
    const float* w1   = (const float*)d_in[1];  // [H,I]
    const float* b1   = (const float*)d_in[2];  // [H]
    const float* w2   = (const float*)d_in[3];  // [O,H]
    const float* b2   = (const float*)d_in[4];  // [O]
    const float* thr1 = (const float*)d_in[5];  // scalar
    const float* thr2 = (const float*)d_in[6];  // scalar

    float* out  = (float*)d_out;
    float* spk1 = out;                                    // [T,B,H]
    float* spk2 = out + (size_t)T_STEPS * BATCH * HID;    // [T,B,O]

    float *cur1, *cur2, *xT, *w1T, *w2T;
    cudaGetSymbolAddress((void**)&cur1, g_cur1);
    cudaGetSymbolAddress((void**)&cur2, g_cur2);
    cudaGetSymbolAddress((void**)&xT,  g_xT);
    cudaGetSymbolAddress((void**)&w1T, g_w1T);
    cudaGetSymbolAddress((void**)&w2T, g_w2T);

    // prep: bit-copy transposes to k-major layouts (launches idx 0-2;
    // GEMM1 phase0 lands at idx 3 = the ncu capture slot)
    transpose32<<<dim3(INDIM / 32, MROWS / 32), dim3(32, 8)>>>(x, xT, MROWS, INDIM);
    transpose32<<<dim3(INDIM / 32, HID / 32), dim3(32, 8)>>>(w1, w1T, HID, INDIM);
    transpose32<<<dim3(HID / 32, OUTDIM / 32), dim3(32, 8)>>>(w2, w2T, OUTDIM, HID);

    // 1) cur1 = X @ W1^T + b1   (two kc=512 panels; AMODE 0, 3-stage ring)
    {
        dim3 grid(HID / BN, MROWS / BM);
        sgemm_panel<0><<<grid, 256>>>(xT, w1T, b1, cur1, MROWS, HID, HID, 0);
        sgemm_panel<0><<<grid, 256>>>(xT + (size_t)KC * MROWS, w1T + (size_t)KC * HID,
                                      b1, cur1, MROWS, HID, HID, 1);
    }
    // 2) LIF layer 1 -> spk1_rec
    lif_scan4<<<(BATCH * HID / 4) / 256, 256>>>(
        (const float4*)cur1, thr1, (float4*)spk1, (BATCH * HID) / 4);

    // 3) cur2 = spk1_rec @ W2^T + b2   (AMODE 1: A m-major, B k-major)
    {
        dim3 grid(OUTDIM / BN, MROWS / BM);
        sgemm_panel<1><<<grid, 256>>>(spk1, w2T, b2, cur2, HID, OUTDIM, OUTDIM, 0);
        sgemm_panel<1><<<grid, 256>>>(spk1 + KC, w2T + (size_t)KC * OUTDIM,
                                      b2, cur2, HID, OUTDIM, OUTDIM, 1);
    }
    // 4) LIF layer 2 -> spk2_rec
    lif_scan1<<<(BATCH * OUTDIM) / 256, 256>>>(cur2, thr2, spk2, BATCH * OUTDIM);
}

// round 10
// speedup vs baseline: 1.0838x; 1.0838x over previous
#include <cuda_runtime.h>
#include <cstdint>

// Problem dims
#define T_STEPS 256
#define BATCH   128
#define INDIM   1024
#define HID     1024
#define OUTDIM  256
#define MROWS   (T_STEPS * BATCH)   // 32768
#define BETA_F  0.9f
#define KC      512                 // Eigen gebp panel depth (bit-exactness contract)

// Scratch (allocation-free rule: __device__ globals)
__device__ float g_cur1[(size_t)MROWS * HID];     // 128 MB
__device__ float g_cur2[(size_t)MROWS * OUTDIM];  // 32 MB
__device__ float g_xT  [(size_t)INDIM * MROWS];   // 128 MB  x transposed (k-major)
__device__ float g_w1T [(size_t)INDIM * HID];     // 4 MB    w1 transposed
__device__ float g_w2T [(size_t)HID * OUTDIM];    // 1 MB    w2 transposed

typedef unsigned long long ull;

// ---- packed f32x2 helpers (each lane = independent IEEE fp32 rn op) --------
__device__ __forceinline__ void ffma2(ull& d, ull a, ull b) {
    asm("fma.rn.f32x2 %0, %1, %2, %0;" : "+l"(d) : "l"(a), "l"(b));
}
__device__ __forceinline__ ull bcast2(float x) {
    ull r; asm("mov.b64 %0, {%1, %1};" : "=l"(r) : "f"(x)); return r;
}
__device__ __forceinline__ void unpack2(float& lo, float& hi, ull v) {
    asm("mov.b64 {%0, %1}, %2;" : "=f"(lo), "=f"(hi) : "l"(v));
}

// ---- cp.async helpers ------------------------------------------------------
__device__ __forceinline__ void cp_async16(uint32_t smem, const void* g) {
    asm volatile("cp.async.cg.shared.global [%0], [%1], 16;" :: "r"(smem), "l"(g));
}
__device__ __forceinline__ void cp_commit() {
    asm volatile("cp.async.commit_group;" ::: "memory");
}
template<int N>
__device__ __forceinline__ void cp_wait() {
    asm volatile("cp.async.wait_group %0;" :: "n"(N) : "memory");
}

// ---------------------------------------------------------------------------
// Tiled transpose: in [rows][cols] -> out [cols][rows]. Pure bit copy.
// ---------------------------------------------------------------------------
__global__ void transpose32(const float* __restrict__ in, float* __restrict__ out,
                            int rows, int cols)
{
    __shared__ float tile[32][33];
    const int c0 = blockIdx.x * 32;
    const int r0 = blockIdx.y * 32;
    #pragma unroll
    for (int j = 0; j < 32; j += 8)
        tile[threadIdx.y + j][threadIdx.x] =
            in[(size_t)(r0 + threadIdx.y + j) * cols + c0 + threadIdx.x];
    __syncthreads();
    #pragma unroll
    for (int j = 0; j < 32; j += 8)
        out[(size_t)(c0 + threadIdx.y + j) * rows + r0 + threadIdx.x] =
            tile[threadIdx.x][threadIdx.y + j];
}

// ---------------------------------------------------------------------------
// SGEMM NT panel (kc=512), FFMA2, cp.async tile loads, 2-stage (R8-proven),
// BK=32 to halve sync frequency.
// Numerics contract (bit-match Eigen gebp kc=512, VERIFIED rel_err==0):
//   per element: S = fadd( chain(k=0..511), chain(k=512..1023) ), chains are
//   ascending-k fp32 FMA chains from 0; then ONE rounded bias add (phase 1).
// AMODE 0: A,B both k-major -> pure cp.async.
// AMODE 1: A m-major (spk1) -> LDG-staged A + STS, cp.async B.
// Tile 128x128x32, 256 threads, microtile 8m(4 f32x2 m-pairs) x 8n.
// ---------------------------------------------------------------------------
#define BM 128
#define BN 128
#define BK 32
#define NITER (KC / BK)   // 16

template<int AMODE>
__global__ __launch_bounds__(256, 2)
void sgemm_panel(const float* __restrict__ A,
                 const float* __restrict__ B,
                 const float* __restrict__ bias,
                 float* __restrict__ C,
                 int lda, int ldb, int N, int addBias)
{
    __shared__ __align__(16) float As[2][BK][BM];
    __shared__ __align__(16) float Bs[2][BK][BN];

    const int tid = threadIdx.x;
    const int bm = blockIdx.y * BM;
    const int bn = blockIdx.x * BN;

    // compute indexing: quadrant layout
    const int tx = (tid & 15) << 2;   // n base (4 wide); second group at +64
    const int ty = (tid >> 4) << 2;   // m base (4 tall); second group at +64

    // cp.async chunk indexing: 32x128-float tile = 1024 chunks of 16B;
    // thread handles rows {lk, lk+8, lk+16, lk+24} at column offset lof.
    const int lk  = tid >> 5;          // 0..7
    const int lof = (tid & 31) << 2;   // 0..124

    // AMODE 1 staging indexing: rows lr, lr+64; 8 k-cols each (2 float4)
    const int lr  = tid >> 2;          // 0..63
    const int lc8 = (tid & 3) << 3;    // 0,8,16,24

    const uint32_t sA = (uint32_t)__cvta_generic_to_shared(&As[0][0][0]);
    const uint32_t sB = (uint32_t)__cvta_generic_to_shared(&Bs[0][0][0]);
    #define SA_ADDR(b, k, off) (sA + (uint32_t)(((b) * BK + (k)) * BM + (off)) * 4u)
    #define SB_ADDR(b, k, off) (sB + (uint32_t)(((b) * BK + (k)) * BN + (off)) * 4u)

    ull acc[4][8];   // panel chains: 4 m-pairs x 8 n
    #pragma unroll
    for (int i = 0; i < 4; i++)
        #pragma unroll
        for (int j = 0; j < 8; j++) acc[i][j] = 0ull;

    // ---- prologue: tile 0 into buffer 0 ----
    #pragma unroll
    for (int r = 0; r < BK; r += 8) {
        cp_async16(SB_ADDR(0, lk + r, lof), &B[(size_t)(lk + r) * ldb + bn + lof]);
    }
    if (AMODE == 0) {
        #pragma unroll
        for (int r = 0; r < BK; r += 8)
            cp_async16(SA_ADDR(0, lk + r, lof), &A[(size_t)(lk + r) * lda + bm + lof]);
    } else {
        #pragma unroll
        for (int h = 0; h < 2; h++) {
            const int row = lr + h * 64;
            float4 a0 = *reinterpret_cast<const float4*>(&A[(size_t)(bm + row) * lda + lc8]);
            float4 a1 = *reinterpret_cast<const float4*>(&A[(size_t)(bm + row) * lda + lc8 + 4]);
            As[0][lc8 + 0][row] = a0.x; As[0][lc8 + 1][row] = a0.y;
            As[0][lc8 + 2][row] = a0.z; As[0][lc8 + 3][row] = a0.w;
            As[0][lc8 + 4][row] = a1.x; As[0][lc8 + 5][row] = a1.y;
            As[0][lc8 + 6][row] = a1.z; As[0][lc8 + 7][row] = a1.w;
        }
    }
    cp_commit();
    cp_wait<0>();
    __syncthreads();

    int buf = 0;
    for (int iter = 0; iter < NITER; iter++) {
        float4 stA[4];
        if (iter + 1 < NITER) {
            const int kt = (iter + 1) * BK;
            const int nb = buf ^ 1;
            #pragma unroll
            for (int r = 0; r < BK; r += 8)
                cp_async16(SB_ADDR(nb, lk + r, lof), &B[(size_t)(kt + lk + r) * ldb + bn + lof]);
            if (AMODE == 0) {
                #pragma unroll
                for (int r = 0; r < BK; r += 8)
                    cp_async16(SA_ADDR(nb, lk + r, lof), &A[(size_t)(kt + lk + r) * lda + bm + lof]);
            } else {
                stA[0] = *reinterpret_cast<const float4*>(&A[(size_t)(bm + lr) * lda + kt + lc8]);
                stA[1] = *reinterpret_cast<const float4*>(&A[(size_t)(bm + lr) * lda + kt + lc8 + 4]);
                stA[2] = *reinterpret_cast<const float4*>(&A[(size_t)(bm + lr + 64) * lda + kt + lc8]);
                stA[3] = *reinterpret_cast<const float4*>(&A[(size_t)(bm + lr + 64) * lda + kt + lc8 + 4]);
            }
            cp_commit();
        }

        // compute: ascending-k FFMA2 chains, lanes paired over M
        #pragma unroll
        for (int k = 0; k < BK; k++) {
            ulonglong2 av0 = *reinterpret_cast<const ulonglong2*>(&As[buf][k][ty]);
            ulonglong2 av1 = *reinterpret_cast<const ulonglong2*>(&As[buf][k][ty + 64]);
            float4 b0 = *reinterpret_cast<const float4*>(&Bs[buf][k][tx]);
            float4 b1 = *reinterpret_cast<const float4*>(&Bs[buf][k][tx + 64]);
            ull ap[4] = {av0.x, av0.y, av1.x, av1.y};
            ull bb[8];
            bb[0] = bcast2(b0.x); bb[1] = bcast2(b0.y);
            bb[2] = bcast2(b0.z); bb[3] = bcast2(b0.w);
            bb[4] = bcast2(b1.x); bb[5] = bcast2(b1.y);
            bb[6] = bcast2(b1.z); bb[7] = bcast2(b1.w);
            #pragma unroll
            for (int i = 0; i < 4; i++)
                #pragma unroll
                for (int j = 0; j < 8; j++)
                    ffma2(acc[i][j], ap[i], bb[j]);
        }

        if (iter + 1 < NITER) {
            const int nb = buf ^ 1;
            if (AMODE == 1) {
                const int row0 = lr, row1 = lr + 64;
                As[nb][lc8 + 0][row0] = stA[0].x; As[nb][lc8 + 1][row0] = stA[0].y;
                As[nb][lc8 + 2][row0] = stA[0].z; As[nb][lc8 + 3][row0] = stA[0].w;
                As[nb][lc8 + 4][row0] = stA[1].x; As[nb][lc8 + 5][row0] = stA[1].y;
                As[nb][lc8 + 6][row0] = stA[1].z; As[nb][lc8 + 7][row0] = stA[1].w;
                As[nb][lc8 + 0][row1] = stA[2].x; As[nb][lc8 + 1][row1] = stA[2].y;
                As[nb][lc8 + 2][row1] = stA[2].z; As[nb][lc8 + 3][row1] = stA[2].w;
                As[nb][lc8 + 4][row1] = stA[3].x; As[nb][lc8 + 5][row1] = stA[3].y;
                As[nb][lc8 + 6][row1] = stA[3].z; As[nb][lc8 + 7][row1] = stA[3].w;
            }
            cp_wait<0>();
            __syncthreads();
            buf = nb;
        }
    }

    // ---- epilogue ----
    if (addBias) {
        // phase 1: v = fadd( fadd(C_panel1, acc_panel2), bias ), per element
        float4 bv0 = *reinterpret_cast<const float4*>(&bias[bn + tx]);
        float4 bv1 = *reinterpret_cast<const float4*>(&bias[bn + tx + 64]);
        const float bb[8] = {bv0.x, bv0.y, bv0.z, bv0.w, bv1.x, bv1.y, bv1.z, bv1.w};
        #pragma unroll
        for (int i = 0; i < 4; i++) {
            int r0 = bm + ((i < 2) ? (ty + 2 * i) : (ty + 64 + 2 * (i - 2)));
            #pragma unroll
            for (int half = 0; half < 2; half++) {
                int row = r0 + half;
                float4 p0 = *reinterpret_cast<const float4*>(&C[(size_t)row * N + bn + tx]);
                float4 p1 = *reinterpret_cast<const float4*>(&C[(size_t)row * N + bn + tx + 64]);
                float pr[8] = {p0.x, p0.y, p0.z, p0.w, p1.x, p1.y, p1.z, p1.w};
                float o[8];
                #pragma unroll
                for (int j = 0; j < 8; j++) {
                    float lo, hi;
                    unpack2(lo, hi, acc[i][j]);
                    float mine = half ? hi : lo;
                    o[j] = __fadd_rn(__fadd_rn(pr[j], mine), bb[j]);
                }
                float4 s0 = {o[0], o[1], o[2], o[3]};
                float4 s1 = {o[4], o[5], o[6], o[7]};
                *reinterpret_cast<float4*>(&C[(size_t)row * N + bn + tx]) = s0;
                *reinterpret_cast<float4*>(&C[(size_t)row * N + bn + tx + 64]) = s1;
            }
        }
    } else {
        // phase 0: store raw panel-1 partials (exact bits)
        #pragma unroll
        for (int i = 0; i < 4; i++) {
            int r0 = bm + ((i < 2) ? (ty + 2 * i) : (ty + 64 + 2 * (i - 2)));
            float lo[8], hi[8];
            #pragma unroll
            for (int j = 0; j < 8; j++) unpack2(lo[j], hi[j], acc[i][j]);
            float4 s0 = {lo[0], lo[1], lo[2], lo[3]};
            float4 s1 = {lo[4], lo[5], lo[6], lo[7]};
            float4 s2 = {hi[0], hi[1], hi[2], hi[3]};
            float4 s3 = {hi[4], hi[5], hi[6], hi[7]};
            *reinterpret_cast<float4*>(&C[(size_t)r0 * N + bn + tx]) = s0;
            *reinterpret_cast<float4*>(&C[(size_t)r0 * N + bn + tx + 64]) = s1;
            *reinterpret_cast<float4*>(&C[(size_t)(r0 + 1) * N + bn + tx]) = s2;
            *reinterpret_cast<float4*>(&C[(size_t)(r0 + 1) * N + bn + tx + 64]) = s3;
        }
    }
    #undef SA_ADDR
    #undef SB_ADDR
}

// ---------------------------------------------------------------------------
// LIF recurrence, XLA-exact op ordering per lane (no FMA contraction).
// Scalar, one neuron per thread, next-t prefetch (loads independent across t).
// ---------------------------------------------------------------------------
__device__ __forceinline__ void lif_step(float& mem, float& s, float c, float thr) {
    float t0 = __fmul_rn(BETA_F, mem);
    float t1 = __fadd_rn(t0, c);
    float t2 = __fmul_rn(s, thr);
    mem = __fsub_rn(t1, t2);
    s = (__fsub_rn(mem, thr) > 0.f) ? 1.0f : 0.0f;
}

__global__ void lif_scan1(const float* __restrict__ cur,
                          const float* __restrict__ thr_p,
                          float* __restrict__ spk_rec,
                          int stride)
{
    const int idx = blockIdx.x * blockDim.x + threadIdx.x;
    const float thr = *thr_p;
    float mem = 0.f, s = 0.f;
    const float* p = cur + idx;
    float* q = spk_rec + idx;
    float c = p[0];
    #pragma unroll 8
    for (int t = 0; t < T_STEPS; t++) {
        float cn = 0.f;
        if (t + 1 < T_STEPS) cn = p[(size_t)(t + 1) * stride];
        lif_step(mem, s, c, thr);
        q[(size_t)t * stride] = s;
        c = cn;
    }
}

// ---------------------------------------------------------------------------
extern "C" void kernel_launch(void* const* d_in, const int* in_sizes, int n_in,
                              void* d_out, int out_size)
{
    const float* x    = (const float*)d_in[0];  // [T,B,I]
    const float* w1   = (const float*)d_in[1];  // [H,I]
    const float* b1   = (const float*)d_in[2];  // [H]
    const float* w2   = (const float*)d_in[3];  // [O,H]
    const float* b2   = (const float*)d_in[4];  // [O]
    const float* thr1 = (const float*)d_in[5];  // scalar
    const float* thr2 = (const float*)d_in[6];  // scalar

    float* out  = (float*)d_out;
    float* spk1 = out;                                    // [T,B,H]
    float* spk2 = out + (size_t)T_STEPS * BATCH * HID;    // [T,B,O]

    float *cur1, *cur2, *xT, *w1T, *w2T;
    cudaGetSymbolAddress((void**)&cur1, g_cur1);
    cudaGetSymbolAddress((void**)&cur2, g_cur2);
    cudaGetSymbolAddress((void**)&xT,  g_xT);
    cudaGetSymbolAddress((void**)&w1T, g_w1T);
    cudaGetSymbolAddress((void**)&w2T, g_w2T);

    // prep: bit-copy transposes to k-major layouts (launch idx 0-2;
    // GEMM1 phase0 lands at idx 3 = the ncu capture slot)
    transpose32<<<dim3(INDIM / 32, MROWS / 32), dim3(32, 8)>>>(x, xT, MROWS, INDIM);
    transpose32<<<dim3(INDIM / 32, HID / 32), dim3(32, 8)>>>(w1, w1T, HID, INDIM);
    transpose32<<<dim3(HID / 32, OUTDIM / 32), dim3(32, 8)>>>(w2, w2T, OUTDIM, HID);

    // 1) cur1 = X @ W1^T + b1   (two kc=512 panels; AMODE 0, 2-stage, BK=32)
    {
        dim3 grid(HID / BN, MROWS / BM);
        sgemm_panel<0><<<grid, 256>>>(xT, w1T, b1, cur1, MROWS, HID, HID, 0);
        sgemm_panel<0><<<grid, 256>>>(xT + (size_t)KC * MROWS, w1T + (size_t)KC * HID,
                                      b1, cur1, MROWS, HID, HID, 1);
    }
    // 2) LIF layer 1 -> spk1_rec  (scalar: 512 blocks, full SM coverage)
    lif_scan1<<<(BATCH * HID) / 256, 256>>>(cur1, thr1, spk1, BATCH * HID);

    // 3) cur2 = spk1_rec @ W2^T + b2   (AMODE 1: A m-major, B k-major)
    {
        dim3 grid(OUTDIM / BN, MROWS / BM);
        sgemm_panel<1><<<grid, 256>>>(spk1, w2T, b2, cur2, HID, OUTDIM, OUTDIM, 0);
        sgemm_panel<1><<<grid, 256>>>(spk1 + KC, w2T + (size_t)KC * OUTDIM,
                                      b2, cur2, HID, OUTDIM, OUTDIM, 1);
    }
    // 4) LIF layer 2 -> spk2_rec
    lif_scan1<<<(BATCH * OUTDIM) / 256, 256>>>(cur2, thr2, spk2, BATCH * OUTDIM);
}